// round 16
// baseline (speedup 1.0000x reference)
#include <cuda_runtime.h>
#include <cuda_bf16.h>
#include <math.h>
#include <stdint.h>

#define B_SZ     2
#define SEQ_L    2048
#define D_MODEL  1024
#define D_INNER  2048
#define D_STATE  16
#define D_CONV   4
#define DT_RANK  64
#define M_TOT    (B_SZ * SEQ_L)              // 4096
#define XD       (DT_RANK + 2 * D_STATE)     // 96
#define KSPLIT   8
#define NCH      (B_SZ * D_INNER)            // 4096 channels
#define SEG      512                         // scan chunk length
#define NSEG     (SEQ_L / SEG)               // 4
#define NCH16    (NCH * D_STATE)             // 65536

// ---------------------------------------------------------------------------
// Scratch (device globals)
// ---------------------------------------------------------------------------
__device__ float g_c1[(size_t)M_TOT * 2 * D_INNER];   // xr = [u_pre | res]
__device__ float g_uconv[(size_t)M_TOT * D_INNER];
__device__ float g_xdbl[(size_t)M_TOT * XD];
__device__ float g_dt[(size_t)M_TOT * D_INNER];
__device__ float g_part[(size_t)KSPLIT * M_TOT * XD]; // split-K partials

// scan chunk state
__device__ float g_hb[(size_t)(NSEG - 1) * NCH16];    // blind h_end, chunks 0..2
__device__ float g_pp[(size_t)(NSEG - 1) * NCH16];    // prod(dA),  chunks 0..2
__device__ float g_hin[(size_t)NSEG * NCH16];         // h at chunk start

// bf16 hi/lo split buffers
__device__ __nv_bfloat16 g_xh[(size_t)M_TOT * D_MODEL];
__device__ __nv_bfloat16 g_xl[(size_t)M_TOT * D_MODEL];
__device__ __nv_bfloat16 g_winth[(size_t)(2 * D_INNER) * D_MODEL]; // W_in^T
__device__ __nv_bfloat16 g_wintl[(size_t)(2 * D_INNER) * D_MODEL];
__device__ __nv_bfloat16 g_woutth[(size_t)D_MODEL * D_INNER];      // W_out^T
__device__ __nv_bfloat16 g_wouttl[(size_t)D_MODEL * D_INNER];
__device__ __nv_bfloat16 g_yh[(size_t)M_TOT * D_INNER];
__device__ __nv_bfloat16 g_yl[(size_t)M_TOT * D_INNER];
__device__ __nv_bfloat16 g_uh[(size_t)M_TOT * D_INNER];            // silu(conv) hi
__device__ __nv_bfloat16 g_ul[(size_t)M_TOT * D_INNER];            // silu(conv) lo
__device__ __nv_bfloat16 g_wxth[(size_t)128 * D_INNER];            // W_xproj^T (pad 128)
__device__ __nv_bfloat16 g_wxtl[(size_t)128 * D_INNER];
__device__ __nv_bfloat16 g_dtlh[(size_t)M_TOT * DT_RANK];          // dt_low hi
__device__ __nv_bfloat16 g_dtll[(size_t)M_TOT * DT_RANK];          // dt_low lo
__device__ __nv_bfloat16 g_wdth[(size_t)D_INNER * DT_RANK];        // W_dt^T hi
__device__ __nv_bfloat16 g_wdtl[(size_t)D_INNER * DT_RANK];        // W_dt^T lo

// ---------------------------------------------------------------------------
// Helpers (baseline PTX only)
// ---------------------------------------------------------------------------
__device__ __forceinline__ uint32_t smem_u32(const void* p) {
    uint32_t r;
    asm("{ .reg .u64 t; cvta.to.shared.u64 t, %1; cvt.u32.u64 %0, t; }"
        : "=r"(r) : "l"(p));
    return r;
}
__device__ __forceinline__ void cpa16(uint32_t dst, const void* src) {
    asm volatile("cp.async.cg.shared.global [%0], [%1], 16;"
                 :: "r"(dst), "l"(src) : "memory");
}
__device__ __forceinline__ void cpa_commit() {
    asm volatile("cp.async.commit_group;" ::: "memory");
}
__device__ __forceinline__ void cpa_wait1() {
    asm volatile("cp.async.wait_group 1;" ::: "memory");
}
__device__ __forceinline__ void cpa_wait0() {
    asm volatile("cp.async.wait_group 0;" ::: "memory");
}
__device__ __forceinline__ void ldm_x4(uint32_t a, uint32_t& r0, uint32_t& r1,
                                       uint32_t& r2, uint32_t& r3) {
    asm volatile("ldmatrix.sync.aligned.m8n8.x4.shared.b16 {%0,%1,%2,%3}, [%4];"
                 : "=r"(r0), "=r"(r1), "=r"(r2), "=r"(r3) : "r"(a));
}
__device__ __forceinline__ void mma_bf16(float& c0, float& c1, float& c2, float& c3,
                                         uint32_t a0, uint32_t a1, uint32_t a2, uint32_t a3,
                                         uint32_t b0, uint32_t b1) {
    asm volatile(
        "mma.sync.aligned.m16n8k16.row.col.f32.bf16.bf16.f32 "
        "{%0,%1,%2,%3}, {%4,%5,%6,%7}, {%8,%9}, {%0,%1,%2,%3};"
        : "+f"(c0), "+f"(c1), "+f"(c2), "+f"(c3)
        : "r"(a0), "r"(a1), "r"(a2), "r"(a3), "r"(b0), "r"(b1));
}

// Swizzled tile: 128 rows x 64B. 16B unit u of row r at r*64 + (u^((r>>1)&3))*16.
__device__ __forceinline__ uint32_t sw_off(int row, int unit) {
    return (uint32_t)((row << 6) + (((unit ^ (row >> 1)) & 3) << 4)
                      + ((unit & ~3) << 4));
}

// ---------------------------------------------------------------------------
// Tensor-core GEMM (HMMA): C[M,*](fp32) = (Ah+Al)[M,K] @ (Bh+Bl)[N,K]^T
//   3-term split. CTA tile 128x128, BK=32, 8 warps. 3-stage cp.async pipeline
//   with swizzled smem, single barrier per chunk, occ 2.
// ---------------------------------------------------------------------------
#define TTILE  8192
#define TBUF   (4 * TTILE)          // 32768 B (Ah,Al,Bh,Bl)
#define TSMEM  (3 * TBUF)           // 98304 B

__device__ __forceinline__ void mm_load(const __nv_bfloat16* __restrict__ base,
                                        int K, int rowTile, int k0, uint32_t sdst)
{
    const int t = threadIdx.x;
    #pragma unroll
    for (int i = 0; i < 2; ++i) {
        const int idx = t + i * 256;            // 0..511
        const int row = idx >> 2;
        const int unit = idx & 3;
        cpa16(sdst + sw_off(row, unit),
              base + (size_t)(rowTile + row) * K + k0 + unit * 8);
    }
}

__device__ __forceinline__ void mm_load4(const __nv_bfloat16* Ah, const __nv_bfloat16* Al,
                                         const __nv_bfloat16* Bh, const __nv_bfloat16* Bl,
                                         int K, int row0, int col0, int ke, uint32_t buf)
{
    mm_load(Ah, K, row0, ke, buf);
    mm_load(Al, K, row0, ke, buf + TTILE);
    mm_load(Bh, K, col0, ke, buf + 2 * TTILE);
    mm_load(Bl, K, col0, ke, buf + 3 * TTILE);
}

__global__ __launch_bounds__(256, 2) void mm_gemm_kernel(
    const __nv_bfloat16* __restrict__ Ah, const __nv_bfloat16* __restrict__ Al,
    const __nv_bfloat16* __restrict__ Bh, const __nv_bfloat16* __restrict__ Bl,
    float* __restrict__ C, int M, int N, int K,
    int ldc, int nstore, int kpart,
    const float* __restrict__ bias, int mode)
{
    extern __shared__ char dsm[];
    const uint32_t sb = smem_u32(dsm);

    const int tid  = threadIdx.x;
    const int lane = tid & 31;
    const int wid  = tid >> 5;
    const int wr   = wid >> 2;
    const int wc   = wid & 3;
    const int row0 = blockIdx.y * 128;
    const int col0 = blockIdx.x * 128;
    const int kbase = blockIdx.z * kpart;
    const int nch  = kpart >> 5;
    if (gridDim.z > 1) C += (size_t)blockIdx.z * M * ldc;

    const int a_row  = lane & 15;
    const int a_unit = lane >> 4;
    const int b_nrow = (lane & 7) + ((lane >> 4) & 1) * 8;
    const int b_unit = (lane >> 3) & 1;

    float acc[4][4][4];
    #pragma unroll
    for (int i = 0; i < 4; i++)
        #pragma unroll
        for (int j = 0; j < 4; j++)
            #pragma unroll
            for (int e = 0; e < 4; e++) acc[i][j][e] = 0.0f;

    mm_load4(Ah, Al, Bh, Bl, K, row0, col0, kbase, sb);
    cpa_commit();
    if (nch > 1) {
        mm_load4(Ah, Al, Bh, Bl, K, row0, col0, kbase + 32, sb + TBUF);
        cpa_commit();
    }

    int s_cur = 0, s_pre = 2;
    for (int c = 0; c < nch; ++c) {
        if (c + 1 < nch) cpa_wait1(); else cpa_wait0();
        __syncthreads();

        if (c + 2 < nch) {
            mm_load4(Ah, Al, Bh, Bl, K, row0, col0, kbase + ((c + 2) << 5),
                     sb + s_pre * TBUF);
            cpa_commit();
        }

        const uint32_t buf = sb + s_cur * TBUF;
        #pragma unroll
        for (int kk = 0; kk < 32; kk += 16) {
            const int ku = kk >> 3;
            uint32_t ah[4][4], al[4][4], bh[2][4], bl[2][4];
            #pragma unroll
            for (int mi = 0; mi < 4; ++mi) {
                const int r = wr * 64 + mi * 16 + a_row;
                const uint32_t ao = buf + sw_off(r, ku + a_unit);
                ldm_x4(ao,          ah[mi][0], ah[mi][1], ah[mi][2], ah[mi][3]);
                ldm_x4(ao + TTILE,  al[mi][0], al[mi][1], al[mi][2], al[mi][3]);
            }
            #pragma unroll
            for (int nb2 = 0; nb2 < 2; ++nb2) {
                const int r = wc * 32 + nb2 * 16 + b_nrow;
                const uint32_t bo = buf + 2 * TTILE + sw_off(r, ku + b_unit);
                ldm_x4(bo,          bh[nb2][0], bh[nb2][1], bh[nb2][2], bh[nb2][3]);
                ldm_x4(bo + TTILE,  bl[nb2][0], bl[nb2][1], bl[nb2][2], bl[nb2][3]);
            }
            #pragma unroll
            for (int mi = 0; mi < 4; ++mi) {
                #pragma unroll
                for (int ni = 0; ni < 4; ++ni) {
                    const int g = ni >> 1, h2 = (ni & 1) * 2;
                    mma_bf16(acc[mi][ni][0], acc[mi][ni][1], acc[mi][ni][2], acc[mi][ni][3],
                             ah[mi][0], ah[mi][1], ah[mi][2], ah[mi][3],
                             bh[g][h2], bh[g][h2 + 1]);
                    mma_bf16(acc[mi][ni][0], acc[mi][ni][1], acc[mi][ni][2], acc[mi][ni][3],
                             ah[mi][0], ah[mi][1], ah[mi][2], ah[mi][3],
                             bl[g][h2], bl[g][h2 + 1]);
                    mma_bf16(acc[mi][ni][0], acc[mi][ni][1], acc[mi][ni][2], acc[mi][ni][3],
                             al[mi][0], al[mi][1], al[mi][2], al[mi][3],
                             bh[g][h2], bh[g][h2 + 1]);
                }
            }
        }
        s_cur = (s_cur == 2) ? 0 : s_cur + 1;
        s_pre = (s_pre == 2) ? 0 : s_pre + 1;
    }

    const int gid = lane >> 2;
    const int t2  = (lane & 3) * 2;
    #pragma unroll
    for (int mi = 0; mi < 4; ++mi) {
        const int r = row0 + wr * 64 + mi * 16 + gid;
        #pragma unroll
        for (int ni = 0; ni < 4; ++ni) {
            const int cc = col0 + wc * 32 + ni * 8 + t2;
            if (cc < nstore) {
                float v0 = acc[mi][ni][0], v1 = acc[mi][ni][1];
                float v2 = acc[mi][ni][2], v3 = acc[mi][ni][3];
                if (mode == 1) {
                    const float b0 = bias[cc], b1 = bias[cc + 1];
                    v0 += b0; v1 += b1; v2 += b0; v3 += b1;
                    v0 = (v0 > 20.0f) ? v0 : log1pf(__expf(v0));
                    v1 = (v1 > 20.0f) ? v1 : log1pf(__expf(v1));
                    v2 = (v2 > 20.0f) ? v2 : log1pf(__expf(v2));
                    v3 = (v3 > 20.0f) ? v3 : log1pf(__expf(v3));
                }
                *(float2*)(C + (size_t)r * ldc + cc)       = make_float2(v0, v1);
                *(float2*)(C + (size_t)(r + 8) * ldc + cc) = make_float2(v2, v3);
            }
        }
    }
}

// ---------------------------------------------------------------------------
// split-K reduce for xproj (+ fused dt_low hi/lo split)
// ---------------------------------------------------------------------------
__global__ void reduce_k_kernel(const float* __restrict__ part,
                                float* __restrict__ out,
                                __nv_bfloat16* __restrict__ dlh,
                                __nv_bfloat16* __restrict__ dll, int n)
{
    int i = blockIdx.x * blockDim.x + threadIdx.x;
    if (i >= n) return;
    float s = 0.0f;
    #pragma unroll
    for (int z = 0; z < KSPLIT; ++z) s += part[(size_t)z * n + i];
    out[i] = s;
    const int col = i % XD;
    if (col < DT_RANK) {
        const int row = i / XD;
        __nv_bfloat16 hb = __float2bfloat16(s);
        dlh[(size_t)row * DT_RANK + col] = hb;
        dll[(size_t)row * DT_RANK + col] =
            __float2bfloat16(s - __bfloat162float(hb));
    }
}

// ---------------------------------------------------------------------------
// fp32 -> bf16 hi/lo split (elementwise)
// ---------------------------------------------------------------------------
__global__ void cvt_hilo_kernel(const float4* __restrict__ s,
                                __nv_bfloat162* __restrict__ h,
                                __nv_bfloat162* __restrict__ l, int n4)
{
    int i = blockIdx.x * blockDim.x + threadIdx.x;
    if (i >= n4) return;
    float4 v = s[i];
    __nv_bfloat16 hx = __float2bfloat16(v.x), hy = __float2bfloat16(v.y);
    __nv_bfloat16 hz = __float2bfloat16(v.z), hw = __float2bfloat16(v.w);
    h[2*i]   = __halves2bfloat162(hx, hy);
    h[2*i+1] = __halves2bfloat162(hz, hw);
    l[2*i]   = __halves2bfloat162(__float2bfloat16(v.x - __bfloat162float(hx)),
                                  __float2bfloat16(v.y - __bfloat162float(hy)));
    l[2*i+1] = __halves2bfloat162(__float2bfloat16(v.z - __bfloat162float(hz)),
                                  __float2bfloat16(v.w - __bfloat162float(hw)));
}

// ---------------------------------------------------------------------------
// Transpose + hi/lo split:  src[R, Cc] fp32 -> out[Cc, R] bf16 (hi, lo)
// ---------------------------------------------------------------------------
__global__ void cvt_t_kernel(const float* __restrict__ s,
                             __nv_bfloat16* __restrict__ h,
                             __nv_bfloat16* __restrict__ l, int R, int Cc)
{
    __shared__ float t[32][33];
    const int c0 = blockIdx.x * 32, r0 = blockIdx.y * 32;
    #pragma unroll
    for (int i = 0; i < 32; i += 8)
        t[threadIdx.y + i][threadIdx.x] =
            s[(size_t)(r0 + threadIdx.y + i) * Cc + c0 + threadIdx.x];
    __syncthreads();
    #pragma unroll
    for (int i = 0; i < 32; i += 8) {
        float v = t[threadIdx.x][threadIdx.y + i];
        __nv_bfloat16 hb = __float2bfloat16(v);
        size_t o = (size_t)(c0 + threadIdx.y + i) * R + r0 + threadIdx.x;
        h[o] = hb;
        l[o] = __float2bfloat16(v - __bfloat162float(hb));
    }
}

// ---------------------------------------------------------------------------
// Causal depthwise conv4 + bias + silu  (+ fused bf16 hi/lo split)
// ---------------------------------------------------------------------------
__global__ void conv_silu_kernel(const float* __restrict__ c1,
                                 const float* __restrict__ w,
                                 const float* __restrict__ bias,
                                 float* __restrict__ out,
                                 __nv_bfloat16* __restrict__ uh,
                                 __nv_bfloat16* __restrict__ ul)
{
    int idx = blockIdx.x * blockDim.x + threadIdx.x;
    if (idx >= M_TOT * D_INNER) return;
    const int d = idx & (D_INNER - 1);
    const int m = idx >> 11;
    const int l = m & (SEQ_L - 1);
    const float* up = c1 + (size_t)(m - l) * (2 * D_INNER) + d;
    float acc = bias[d];
    #pragma unroll
    for (int k = 0; k < D_CONV; k++) {
        int ll = l + k - (D_CONV - 1);
        if (ll >= 0)
            acc = fmaf(up[(size_t)ll * (2 * D_INNER)], w[d * D_CONV + k], acc);
    }
    const float v = acc * (1.0f / (1.0f + __expf(-acc)));
    out[idx] = v;
    __nv_bfloat16 hb = __float2bfloat16(v);
    uh[idx] = hb;
    ul[idx] = __float2bfloat16(v - __bfloat162float(hb));
}

// ---------------------------------------------------------------------------
// Chunked selective scan. Lane layout: 8 lanes/channel, 2 states/lane,
// 4 channels/warp.
// Pass A: chunks 0..NSEG-2: blind h_end + prod(dA). No C loads, no shfl.
// Pass C: h_in[k] = P[k-1]*h_in[k-1] + hb[k-1]  (exact composition)
// Pass B: all chunks in parallel from exact h_in; FUSED epilogue computes
//         y_final = (p + u*D) * silu(res) and stores bf16 hi/lo directly.
// ---------------------------------------------------------------------------
__global__ __launch_bounds__(256) void scanA_kernel(
    const float* __restrict__ xdbl, const float* __restrict__ dt,
    const float* __restrict__ u, const float* __restrict__ A_log,
    float* __restrict__ hb, float* __restrict__ pp)
{
    const int lane = threadIdx.x & 31;
    const int w    = threadIdx.x >> 5;
    const int chw  = lane >> 3;
    const int sp   = lane & 7;
    const int c    = blockIdx.x * 32 + w * 4 + chw;
    const int chunk = blockIdx.y;                    // 0..NSEG-2
    const int l0   = chunk * SEG;
    const int b    = c >> 11;
    const int d    = c & (D_INNER - 1);

    const float LOG2E = 1.4426950408889634f;
    const float Ae0 = -__expf(A_log[d * D_STATE + 2 * sp])     * LOG2E;
    const float Ae1 = -__expf(A_log[d * D_STATE + 2 * sp + 1]) * LOG2E;

    const float* dtp = dt   + (size_t)b * SEQ_L * D_INNER + d;
    const float* up  = u    + (size_t)b * SEQ_L * D_INNER + d;
    const float* xb  = xdbl + (size_t)b * SEQ_L * XD + DT_RANK + 2 * sp;

    float h0 = 0.f, h1 = 0.f, P0 = 1.f, P1 = 1.f;

    float  rdt[8], ru[8];
    float2 rB[8];
#define SA_LOAD(o, slot) do {                                               \
        if ((o) < SEQ_L) {                                                  \
            rdt[slot] = dtp[(size_t)(o) * D_INNER];                         \
            ru [slot] = up [(size_t)(o) * D_INNER];                         \
            rB [slot] = *(const float2*)(xb + (size_t)(o) * XD);            \
        } else { rdt[slot] = 0.f; ru[slot] = 0.f;                           \
                 rB[slot] = make_float2(0.f, 0.f); }                        \
    } while (0)

    #pragma unroll
    for (int j = 0; j < 8; ++j) SA_LOAD(l0 + j, j);

    for (int li = 0; li < SEG; li += 8) {
        #pragma unroll
        for (int j = 0; j < 8; ++j) {
            const float  dtv = rdt[j];
            const float  uv  = ru[j];
            const float2 Bv  = rB[j];
            SA_LOAD(l0 + li + j + 8, j);

            const float cu  = dtv * uv;
            const float dA0 = exp2f(dtv * Ae0);
            const float dA1 = exp2f(dtv * Ae1);
            h0 = fmaf(dA0, h0, cu * Bv.x);
            h1 = fmaf(dA1, h1, cu * Bv.y);
            P0 *= dA0;
            P1 *= dA1;
        }
    }
#undef SA_LOAD
    const size_t o = (size_t)chunk * NCH16 + (size_t)c * D_STATE + 2 * sp;
    hb[o]     = h0;  hb[o + 1] = h1;
    pp[o]     = P0;  pp[o + 1] = P1;
}

__global__ void scanC_kernel(const float* __restrict__ hb,
                             const float* __restrict__ pp,
                             float* __restrict__ hin)
{
    int i = blockIdx.x * blockDim.x + threadIdx.x;
    if (i >= NCH16) return;
    float h = 0.f;
    hin[i] = 0.f;
    #pragma unroll
    for (int k = 1; k < NSEG; ++k) {
        h = fmaf(pp[(size_t)(k - 1) * NCH16 + i], h,
                 hb[(size_t)(k - 1) * NCH16 + i]);
        hin[(size_t)k * NCH16 + i] = h;
    }
}

__global__ __launch_bounds__(256) void scanB_kernel(
    const float* __restrict__ xdbl, const float* __restrict__ dt,
    const float* __restrict__ u, const float* __restrict__ A_log,
    const float* __restrict__ hin,
    const float* __restrict__ c1,          // res = c1[., D_INNER + d]
    const float* __restrict__ Dp,
    __nv_bfloat16* __restrict__ yh, __nv_bfloat16* __restrict__ yl)
{
    const int lane = threadIdx.x & 31;
    const int w    = threadIdx.x >> 5;
    const int chw  = lane >> 3;
    const int sp   = lane & 7;
    const int c    = blockIdx.x * 32 + w * 4 + chw;
    const int chunk = blockIdx.y;                    // 0..NSEG-1
    const int l0   = chunk * SEG;
    const int b    = c >> 11;
    const int d    = c & (D_INNER - 1);

    const float LOG2E = 1.4426950408889634f;
    const float Ae0 = -__expf(A_log[d * D_STATE + 2 * sp])     * LOG2E;
    const float Ae1 = -__expf(A_log[d * D_STATE + 2 * sp + 1]) * LOG2E;
    const float Dv  = Dp[d];

    const float* dtp = dt   + (size_t)b * SEQ_L * D_INNER + d;
    const float* up  = u    + (size_t)b * SEQ_L * D_INNER + d;
    const float* xb  = xdbl + (size_t)b * SEQ_L * XD + DT_RANK + 2 * sp;
    const float* rp  = c1   + (size_t)b * SEQ_L * (2 * D_INNER) + D_INNER + d;
    __nv_bfloat16* yhp = yh + (size_t)b * SEQ_L * D_INNER + d;
    __nv_bfloat16* ylp = yl + (size_t)b * SEQ_L * D_INNER + d;

    const size_t ho = (size_t)chunk * NCH16 + (size_t)c * D_STATE + 2 * sp;
    float h0 = hin[ho];
    float h1 = hin[ho + 1];

    float  rdt[8], ru[8], rres[8];
    float2 rB[8], rC[8];
#define SB_LOAD(o, slot) do {                                               \
        if ((o) < SEQ_L) {                                                  \
            rdt[slot]  = dtp[(size_t)(o) * D_INNER];                        \
            ru [slot]  = up [(size_t)(o) * D_INNER];                        \
            rres[slot] = rp [(size_t)(o) * (2 * D_INNER)];                  \
            rB [slot]  = *(const float2*)(xb + (size_t)(o) * XD);           \
            rC [slot]  = *(const float2*)(xb + (size_t)(o) * XD + D_STATE); \
        } else {                                                            \
            rdt[slot] = 0.f; ru[slot] = 0.f; rres[slot] = 0.f;              \
            rB[slot] = make_float2(0.f, 0.f);                               \
            rC[slot] = make_float2(0.f, 0.f);                               \
        }                                                                   \
    } while (0)

    #pragma unroll
    for (int j = 0; j < 8; ++j) SB_LOAD(l0 + j, j);

    for (int li = 0; li < SEG; li += 8) {
        #pragma unroll
        for (int j = 0; j < 8; ++j) {
            const int l = l0 + li + j;
            const float  dtv  = rdt[j];
            const float  uv   = ru[j];
            const float  resv = rres[j];
            const float2 Bv   = rB[j];
            const float2 Cv   = rC[j];
            SB_LOAD(l + 8, j);

            const float cu  = dtv * uv;
            const float dA0 = exp2f(dtv * Ae0);
            const float dA1 = exp2f(dtv * Ae1);
            h0 = fmaf(dA0, h0, cu * Bv.x);
            h1 = fmaf(dA1, h1, cu * Bv.y);

            float p = h0 * Cv.x;
            p = fmaf(h1, Cv.y, p);
            p += __shfl_xor_sync(0xffffffffu, p, 1);
            p += __shfl_xor_sync(0xffffffffu, p, 2);
            p += __shfl_xor_sync(0xffffffffu, p, 4);
            if (sp == 0) {
                // fused combine: v = (p + u*D) * silu(res), split to bf16 hi/lo
                const float sres = resv * (1.0f / (1.0f + __expf(-resv)));
                const float v = fmaf(uv, Dv, p) * sres;
                const __nv_bfloat16 hb2 = __float2bfloat16(v);
                yhp[(size_t)l * D_INNER] = hb2;
                ylp[(size_t)l * D_INNER] =
                    __float2bfloat16(v - __bfloat162float(hb2));
            }
        }
    }
#undef SB_LOAD
}

// ---------------------------------------------------------------------------
// Launch
// ---------------------------------------------------------------------------
extern "C" void kernel_launch(void* const* d_in, const int* in_sizes, int n_in,
                              void* d_out, int out_size)
{
    const float* x       = (const float*)d_in[0];
    const float* W_in    = (const float*)d_in[1];
    const float* conv_w  = (const float*)d_in[2];
    const float* conv_b  = (const float*)d_in[3];
    const float* W_xproj = (const float*)d_in[4];
    const float* W_dt    = (const float*)d_in[5];
    const float* b_dt    = (const float*)d_in[6];
    const float* A_log   = (const float*)d_in[7];
    const float* Dp      = (const float*)d_in[8];
    const float* W_out   = (const float*)d_in[9];
    float* out = (float*)d_out;

    float *c1, *uconv, *xdbl, *dtb, *part, *hbp, *ppp, *hinp;
    __nv_bfloat16 *xh, *xl, *wth, *wtl, *woh, *wol, *yh, *yl, *uh, *ul;
    __nv_bfloat16 *wxh, *wxl, *dtlh, *dtll, *wdth, *wdtl;
    cudaGetSymbolAddress((void**)&c1,    g_c1);
    cudaGetSymbolAddress((void**)&uconv, g_uconv);
    cudaGetSymbolAddress((void**)&xdbl,  g_xdbl);
    cudaGetSymbolAddress((void**)&dtb,   g_dt);
    cudaGetSymbolAddress((void**)&part,  g_part);
    cudaGetSymbolAddress((void**)&hbp,   g_hb);
    cudaGetSymbolAddress((void**)&ppp,   g_pp);
    cudaGetSymbolAddress((void**)&hinp,  g_hin);
    cudaGetSymbolAddress((void**)&xh,    g_xh);
    cudaGetSymbolAddress((void**)&xl,    g_xl);
    cudaGetSymbolAddress((void**)&wth,   g_winth);
    cudaGetSymbolAddress((void**)&wtl,   g_wintl);
    cudaGetSymbolAddress((void**)&woh,   g_woutth);
    cudaGetSymbolAddress((void**)&wol,   g_wouttl);
    cudaGetSymbolAddress((void**)&yh,    g_yh);
    cudaGetSymbolAddress((void**)&yl,    g_yl);
    cudaGetSymbolAddress((void**)&uh,    g_uh);
    cudaGetSymbolAddress((void**)&ul,    g_ul);
    cudaGetSymbolAddress((void**)&wxh,   g_wxth);
    cudaGetSymbolAddress((void**)&wxl,   g_wxtl);
    cudaGetSymbolAddress((void**)&dtlh,  g_dtlh);
    cudaGetSymbolAddress((void**)&dtll,  g_dtll);
    cudaGetSymbolAddress((void**)&wdth,  g_wdth);
    cudaGetSymbolAddress((void**)&wdtl,  g_wdtl);

    cudaFuncSetAttribute(mm_gemm_kernel,
                         cudaFuncAttributeMaxDynamicSharedMemorySize, TSMEM);

    dim3 blk(256);
    dim3 tb(32, 8);

    // launches #1-#3: conversions needed by GEMM1
    {
        int n4 = (M_TOT * D_MODEL) / 4;
        cvt_hilo_kernel<<<(n4 + 255) / 256, blk>>>((const float4*)x,
                                                   (__nv_bfloat162*)xh,
                                                   (__nv_bfloat162*)xl, n4);
        cvt_t_kernel<<<dim3((2 * D_INNER) / 32, D_MODEL / 32), tb>>>(
            W_in, wth, wtl, D_MODEL, 2 * D_INNER);
        cvt_t_kernel<<<dim3(D_MODEL / 32, D_INNER / 32), tb>>>(
            W_out, woh, wol, D_INNER, D_MODEL);
    }

    // launch #4 (ncu-profiled slot): xr = x @ W_in  (HMMA) [4096x4096x1024]
    {
        dim3 grid((2 * D_INNER) / 128, M_TOT / 128, 1);
        mm_gemm_kernel<<<grid, blk, TSMEM>>>(xh, xl, wth, wtl, c1,
                                             M_TOT, 2 * D_INNER, D_MODEL,
                                             2 * D_INNER, 2 * D_INNER, D_MODEL,
                                             nullptr, 0);
    }

    // remaining weight conversions
    {
        cvt_t_kernel<<<dim3(XD / 32, D_INNER / 32), tb>>>(
            W_xproj, wxh, wxl, D_INNER, XD);
        cvt_t_kernel<<<dim3(D_INNER / 32, DT_RANK / 32), tb>>>(
            W_dt, wdth, wdtl, DT_RANK, D_INNER);
    }

    // causal conv + silu (+ hi/lo split)
    {
        int total = M_TOT * D_INNER;
        conv_silu_kernel<<<(total + 255) / 256, blk>>>(c1, conv_w, conv_b,
                                                       uconv, uh, ul);
    }

    // x_dbl = uconv @ W_xproj  (HMMA split-K)  [4096 x 96 x 2048]
    {
        dim3 grid(1, M_TOT / 128, KSPLIT);
        mm_gemm_kernel<<<grid, blk, TSMEM>>>(uh, ul, wxh, wxl, part,
                                             M_TOT, 128, D_INNER,
                                             XD, XD, D_INNER / KSPLIT,
                                             nullptr, 0);
        int n = M_TOT * XD;
        reduce_k_kernel<<<(n + 255) / 256, blk>>>(part, xdbl, dtlh, dtll, n);
    }

    // dt = softplus(dt_low @ W_dt + b_dt)  (HMMA)  [4096 x 2048 x 64]
    {
        dim3 grid(D_INNER / 128, M_TOT / 128, 1);
        mm_gemm_kernel<<<grid, blk, TSMEM>>>(dtlh, dtll, wdth, wdtl, dtb,
                                             M_TOT, D_INNER, DT_RANK,
                                             D_INNER, D_INNER, DT_RANK,
                                             b_dt, 1);
    }

    // chunked selective scan: A -> C -> B (B has fused combine epilogue)
    {
        scanA_kernel<<<dim3(NCH / 32, NSEG - 1), blk>>>(xdbl, dtb, uconv,
                                                        A_log, hbp, ppp);
        scanC_kernel<<<(NCH16 + 255) / 256, blk>>>(hbp, ppp, hinp);
        scanB_kernel<<<dim3(NCH / 32, NSEG), blk>>>(xdbl, dtb, uconv, A_log,
                                                    hinp, c1, Dp, yh, yl);
    }

    // out = y @ W_out  (HMMA)  [4096 x 1024 x 2048]
    {
        dim3 grid(D_MODEL / 128, M_TOT / 128, 1);
        mm_gemm_kernel<<<grid, blk, TSMEM>>>(yh, yl, woh, wol, out,
                                             M_TOT, D_MODEL, D_INNER,
                                             D_MODEL, D_MODEL, D_INNER,
                                             nullptr, 0);
    }
}

// round 17
// speedup vs baseline: 1.2163x; 1.2163x over previous
#include <cuda_runtime.h>
#include <cuda_bf16.h>
#include <math.h>
#include <stdint.h>

#define B_SZ     2
#define SEQ_L    2048
#define D_MODEL  1024
#define D_INNER  2048
#define D_STATE  16
#define D_CONV   4
#define DT_RANK  64
#define M_TOT    (B_SZ * SEQ_L)              // 4096
#define XD       (DT_RANK + 2 * D_STATE)     // 96
#define KSPLIT   8
#define NCH      (B_SZ * D_INNER)            // 4096 channels
#define SEG      512                         // scan chunk length
#define NSEG     (SEQ_L / SEG)               // 4
#define NCH16    (NCH * D_STATE)             // 65536

// ---------------------------------------------------------------------------
// Scratch (device globals)
// ---------------------------------------------------------------------------
__device__ float g_c1[(size_t)M_TOT * 2 * D_INNER];   // xr = [u_pre | res]
__device__ float g_uconv[(size_t)M_TOT * D_INNER];
__device__ float g_xdbl[(size_t)M_TOT * XD];
__device__ float g_dt[(size_t)M_TOT * D_INNER];
__device__ float g_y[(size_t)M_TOT * D_INNER];
__device__ float g_part[(size_t)KSPLIT * M_TOT * XD]; // split-K partials

// scan chunk state
__device__ float g_hb[(size_t)(NSEG - 1) * NCH16];
__device__ float g_pp[(size_t)(NSEG - 1) * NCH16];
__device__ float g_hin[(size_t)NSEG * NCH16];

// bf16 hi/lo split buffers
__device__ __nv_bfloat16 g_xh[(size_t)M_TOT * D_MODEL];
__device__ __nv_bfloat16 g_xl[(size_t)M_TOT * D_MODEL];
__device__ __nv_bfloat16 g_winth[(size_t)(2 * D_INNER) * D_MODEL]; // W_in^T
__device__ __nv_bfloat16 g_wintl[(size_t)(2 * D_INNER) * D_MODEL];
__device__ __nv_bfloat16 g_woutth[(size_t)D_MODEL * D_INNER];      // W_out^T
__device__ __nv_bfloat16 g_wouttl[(size_t)D_MODEL * D_INNER];
__device__ __nv_bfloat16 g_yh[(size_t)M_TOT * D_INNER];
__device__ __nv_bfloat16 g_yl[(size_t)M_TOT * D_INNER];
__device__ __nv_bfloat16 g_uh[(size_t)M_TOT * D_INNER];            // silu(conv) hi
__device__ __nv_bfloat16 g_ul[(size_t)M_TOT * D_INNER];            // silu(conv) lo
__device__ __nv_bfloat16 g_wxth[(size_t)128 * D_INNER];            // W_xproj^T (pad 128)
__device__ __nv_bfloat16 g_wxtl[(size_t)128 * D_INNER];
__device__ __nv_bfloat16 g_dtlh[(size_t)M_TOT * DT_RANK];          // dt_low hi
__device__ __nv_bfloat16 g_dtll[(size_t)M_TOT * DT_RANK];          // dt_low lo
__device__ __nv_bfloat16 g_wdth[(size_t)D_INNER * DT_RANK];        // W_dt^T hi
__device__ __nv_bfloat16 g_wdtl[(size_t)D_INNER * DT_RANK];        // W_dt^T lo

// ---------------------------------------------------------------------------
// Helpers (baseline PTX only)
// ---------------------------------------------------------------------------
__device__ __forceinline__ uint32_t smem_u32(const void* p) {
    uint32_t r;
    asm("{ .reg .u64 t; cvta.to.shared.u64 t, %1; cvt.u32.u64 %0, t; }"
        : "=r"(r) : "l"(p));
    return r;
}
__device__ __forceinline__ void cpa16(uint32_t dst, const void* src) {
    asm volatile("cp.async.cg.shared.global [%0], [%1], 16;"
                 :: "r"(dst), "l"(src) : "memory");
}
__device__ __forceinline__ void cpa_commit() {
    asm volatile("cp.async.commit_group;" ::: "memory");
}
__device__ __forceinline__ void cpa_wait1() {
    asm volatile("cp.async.wait_group 1;" ::: "memory");
}
__device__ __forceinline__ void cpa_wait0() {
    asm volatile("cp.async.wait_group 0;" ::: "memory");
}
__device__ __forceinline__ void ldm_x4(uint32_t a, uint32_t& r0, uint32_t& r1,
                                       uint32_t& r2, uint32_t& r3) {
    asm volatile("ldmatrix.sync.aligned.m8n8.x4.shared.b16 {%0,%1,%2,%3}, [%4];"
                 : "=r"(r0), "=r"(r1), "=r"(r2), "=r"(r3) : "r"(a));
}
__device__ __forceinline__ void mma_bf16(float& c0, float& c1, float& c2, float& c3,
                                         uint32_t a0, uint32_t a1, uint32_t a2, uint32_t a3,
                                         uint32_t b0, uint32_t b1) {
    asm volatile(
        "mma.sync.aligned.m16n8k16.row.col.f32.bf16.bf16.f32 "
        "{%0,%1,%2,%3}, {%4,%5,%6,%7}, {%8,%9}, {%0,%1,%2,%3};"
        : "+f"(c0), "+f"(c1), "+f"(c2), "+f"(c3)
        : "r"(a0), "r"(a1), "r"(a2), "r"(a3), "r"(b0), "r"(b1));
}

// Swizzled tile: 128 rows x 64B. 16B unit u of row r at r*64 + (u^((r>>1)&3))*16.
__device__ __forceinline__ uint32_t sw_off(int row, int unit) {
    return (uint32_t)((row << 6) + (((unit ^ (row >> 1)) & 3) << 4)
                      + ((unit & ~3) << 4));
}

// ---------------------------------------------------------------------------
// Tensor-core GEMM (HMMA): C[M,*](fp32) = (Ah+Al)[M,K] @ (Bh+Bl)[N,K]^T
//   3-term split. CTA tile 128x128, BK=32, 8 warps. 3-stage cp.async pipeline
//   with swizzled smem, single barrier per chunk, occ 2.
// ---------------------------------------------------------------------------
#define TTILE  8192
#define TBUF   (4 * TTILE)          // 32768 B (Ah,Al,Bh,Bl)
#define TSMEM  (3 * TBUF)           // 98304 B

__device__ __forceinline__ void mm_load(const __nv_bfloat16* __restrict__ base,
                                        int K, int rowTile, int k0, uint32_t sdst)
{
    const int t = threadIdx.x;
    #pragma unroll
    for (int i = 0; i < 2; ++i) {
        const int idx = t + i * 256;            // 0..511
        const int row = idx >> 2;
        const int unit = idx & 3;
        cpa16(sdst + sw_off(row, unit),
              base + (size_t)(rowTile + row) * K + k0 + unit * 8);
    }
}

__device__ __forceinline__ void mm_load4(const __nv_bfloat16* Ah, const __nv_bfloat16* Al,
                                         const __nv_bfloat16* Bh, const __nv_bfloat16* Bl,
                                         int K, int row0, int col0, int ke, uint32_t buf)
{
    mm_load(Ah, K, row0, ke, buf);
    mm_load(Al, K, row0, ke, buf + TTILE);
    mm_load(Bh, K, col0, ke, buf + 2 * TTILE);
    mm_load(Bl, K, col0, ke, buf + 3 * TTILE);
}

__global__ __launch_bounds__(256, 2) void mm_gemm_kernel(
    const __nv_bfloat16* __restrict__ Ah, const __nv_bfloat16* __restrict__ Al,
    const __nv_bfloat16* __restrict__ Bh, const __nv_bfloat16* __restrict__ Bl,
    float* __restrict__ C, int M, int N, int K,
    int ldc, int nstore, int kpart,
    const float* __restrict__ bias, int mode)
{
    extern __shared__ char dsm[];
    const uint32_t sb = smem_u32(dsm);

    const int tid  = threadIdx.x;
    const int lane = tid & 31;
    const int wid  = tid >> 5;
    const int wr   = wid >> 2;
    const int wc   = wid & 3;
    const int row0 = blockIdx.y * 128;
    const int col0 = blockIdx.x * 128;
    const int kbase = blockIdx.z * kpart;
    const int nch  = kpart >> 5;
    if (gridDim.z > 1) C += (size_t)blockIdx.z * M * ldc;

    const int a_row  = lane & 15;
    const int a_unit = lane >> 4;
    const int b_nrow = (lane & 7) + ((lane >> 4) & 1) * 8;
    const int b_unit = (lane >> 3) & 1;

    float acc[4][4][4];
    #pragma unroll
    for (int i = 0; i < 4; i++)
        #pragma unroll
        for (int j = 0; j < 4; j++)
            #pragma unroll
            for (int e = 0; e < 4; e++) acc[i][j][e] = 0.0f;

    mm_load4(Ah, Al, Bh, Bl, K, row0, col0, kbase, sb);
    cpa_commit();
    if (nch > 1) {
        mm_load4(Ah, Al, Bh, Bl, K, row0, col0, kbase + 32, sb + TBUF);
        cpa_commit();
    }

    int s_cur = 0, s_pre = 2;
    for (int c = 0; c < nch; ++c) {
        if (c + 1 < nch) cpa_wait1(); else cpa_wait0();
        __syncthreads();

        if (c + 2 < nch) {
            mm_load4(Ah, Al, Bh, Bl, K, row0, col0, kbase + ((c + 2) << 5),
                     sb + s_pre * TBUF);
            cpa_commit();
        }

        const uint32_t buf = sb + s_cur * TBUF;
        #pragma unroll
        for (int kk = 0; kk < 32; kk += 16) {
            const int ku = kk >> 3;
            uint32_t ah[4][4], al[4][4], bh[2][4], bl[2][4];
            #pragma unroll
            for (int mi = 0; mi < 4; ++mi) {
                const int r = wr * 64 + mi * 16 + a_row;
                const uint32_t ao = buf + sw_off(r, ku + a_unit);
                ldm_x4(ao,          ah[mi][0], ah[mi][1], ah[mi][2], ah[mi][3]);
                ldm_x4(ao + TTILE,  al[mi][0], al[mi][1], al[mi][2], al[mi][3]);
            }
            #pragma unroll
            for (int nb2 = 0; nb2 < 2; ++nb2) {
                const int r = wc * 32 + nb2 * 16 + b_nrow;
                const uint32_t bo = buf + 2 * TTILE + sw_off(r, ku + b_unit);
                ldm_x4(bo,          bh[nb2][0], bh[nb2][1], bh[nb2][2], bh[nb2][3]);
                ldm_x4(bo + TTILE,  bl[nb2][0], bl[nb2][1], bl[nb2][2], bl[nb2][3]);
            }
            #pragma unroll
            for (int mi = 0; mi < 4; ++mi) {
                #pragma unroll
                for (int ni = 0; ni < 4; ++ni) {
                    const int g = ni >> 1, h2 = (ni & 1) * 2;
                    mma_bf16(acc[mi][ni][0], acc[mi][ni][1], acc[mi][ni][2], acc[mi][ni][3],
                             ah[mi][0], ah[mi][1], ah[mi][2], ah[mi][3],
                             bh[g][h2], bh[g][h2 + 1]);
                    mma_bf16(acc[mi][ni][0], acc[mi][ni][1], acc[mi][ni][2], acc[mi][ni][3],
                             ah[mi][0], ah[mi][1], ah[mi][2], ah[mi][3],
                             bl[g][h2], bl[g][h2 + 1]);
                    mma_bf16(acc[mi][ni][0], acc[mi][ni][1], acc[mi][ni][2], acc[mi][ni][3],
                             al[mi][0], al[mi][1], al[mi][2], al[mi][3],
                             bh[g][h2], bh[g][h2 + 1]);
                }
            }
        }
        s_cur = (s_cur == 2) ? 0 : s_cur + 1;
        s_pre = (s_pre == 2) ? 0 : s_pre + 1;
    }

    const int gid = lane >> 2;
    const int t2  = (lane & 3) * 2;
    #pragma unroll
    for (int mi = 0; mi < 4; ++mi) {
        const int r = row0 + wr * 64 + mi * 16 + gid;
        #pragma unroll
        for (int ni = 0; ni < 4; ++ni) {
            const int cc = col0 + wc * 32 + ni * 8 + t2;
            if (cc < nstore) {
                float v0 = acc[mi][ni][0], v1 = acc[mi][ni][1];
                float v2 = acc[mi][ni][2], v3 = acc[mi][ni][3];
                if (mode == 1) {
                    const float b0 = bias[cc], b1 = bias[cc + 1];
                    v0 += b0; v1 += b1; v2 += b0; v3 += b1;
                    v0 = (v0 > 20.0f) ? v0 : log1pf(__expf(v0));
                    v1 = (v1 > 20.0f) ? v1 : log1pf(__expf(v1));
                    v2 = (v2 > 20.0f) ? v2 : log1pf(__expf(v2));
                    v3 = (v3 > 20.0f) ? v3 : log1pf(__expf(v3));
                }
                *(float2*)(C + (size_t)r * ldc + cc)       = make_float2(v0, v1);
                *(float2*)(C + (size_t)(r + 8) * ldc + cc) = make_float2(v2, v3);
            }
        }
    }
}

// ---------------------------------------------------------------------------
// split-K reduce for xproj (+ fused dt_low hi/lo split)
// ---------------------------------------------------------------------------
__global__ void reduce_k_kernel(const float* __restrict__ part,
                                float* __restrict__ out,
                                __nv_bfloat16* __restrict__ dlh,
                                __nv_bfloat16* __restrict__ dll, int n)
{
    int i = blockIdx.x * blockDim.x + threadIdx.x;
    if (i >= n) return;
    float s = 0.0f;
    #pragma unroll
    for (int z = 0; z < KSPLIT; ++z) s += part[(size_t)z * n + i];
    out[i] = s;
    const int col = i % XD;
    if (col < DT_RANK) {
        const int row = i / XD;
        __nv_bfloat16 hb = __float2bfloat16(s);
        dlh[(size_t)row * DT_RANK + col] = hb;
        dll[(size_t)row * DT_RANK + col] =
            __float2bfloat16(s - __bfloat162float(hb));
    }
}

// ---------------------------------------------------------------------------
// fp32 -> bf16 hi/lo split (elementwise)
// ---------------------------------------------------------------------------
__global__ void cvt_hilo_kernel(const float4* __restrict__ s,
                                __nv_bfloat162* __restrict__ h,
                                __nv_bfloat162* __restrict__ l, int n4)
{
    int i = blockIdx.x * blockDim.x + threadIdx.x;
    if (i >= n4) return;
    float4 v = s[i];
    __nv_bfloat16 hx = __float2bfloat16(v.x), hy = __float2bfloat16(v.y);
    __nv_bfloat16 hz = __float2bfloat16(v.z), hw = __float2bfloat16(v.w);
    h[2*i]   = __halves2bfloat162(hx, hy);
    h[2*i+1] = __halves2bfloat162(hz, hw);
    l[2*i]   = __halves2bfloat162(__float2bfloat16(v.x - __bfloat162float(hx)),
                                  __float2bfloat16(v.y - __bfloat162float(hy)));
    l[2*i+1] = __halves2bfloat162(__float2bfloat16(v.z - __bfloat162float(hz)),
                                  __float2bfloat16(v.w - __bfloat162float(hw)));
}

// ---------------------------------------------------------------------------
// Transpose + hi/lo split:  src[R, Cc] fp32 -> out[Cc, R] bf16 (hi, lo)
// ---------------------------------------------------------------------------
__global__ void cvt_t_kernel(const float* __restrict__ s,
                             __nv_bfloat16* __restrict__ h,
                             __nv_bfloat16* __restrict__ l, int R, int Cc)
{
    __shared__ float t[32][33];
    const int c0 = blockIdx.x * 32, r0 = blockIdx.y * 32;
    #pragma unroll
    for (int i = 0; i < 32; i += 8)
        t[threadIdx.y + i][threadIdx.x] =
            s[(size_t)(r0 + threadIdx.y + i) * Cc + c0 + threadIdx.x];
    __syncthreads();
    #pragma unroll
    for (int i = 0; i < 32; i += 8) {
        float v = t[threadIdx.x][threadIdx.y + i];
        __nv_bfloat16 hb = __float2bfloat16(v);
        size_t o = (size_t)(c0 + threadIdx.y + i) * R + r0 + threadIdx.x;
        h[o] = hb;
        l[o] = __float2bfloat16(v - __bfloat162float(hb));
    }
}

// ---------------------------------------------------------------------------
// Causal depthwise conv4 + bias + silu (+ fused hi/lo split), 2 elems/thread
// ---------------------------------------------------------------------------
__global__ void conv_silu_kernel(const float* __restrict__ c1,
                                 const float* __restrict__ w,
                                 const float* __restrict__ bias,
                                 float* __restrict__ out,
                                 __nv_bfloat16* __restrict__ uh,
                                 __nv_bfloat16* __restrict__ ul)
{
    int i2 = blockIdx.x * blockDim.x + threadIdx.x;     // pair index
    if (i2 >= (M_TOT * D_INNER) / 2) return;
    const int idx = i2 * 2;
    const int d = idx & (D_INNER - 1);
    const int m = idx >> 11;
    const int l = m & (SEQ_L - 1);
    const float* up = c1 + (size_t)(m - l) * (2 * D_INNER) + d;
    const float4 w0 = *(const float4*)(w + d * D_CONV);
    const float4 w1 = *(const float4*)(w + (d + 1) * D_CONV);
    const float2 bs = *(const float2*)(bias + d);
    float a0 = bs.x, a1 = bs.y;
    #pragma unroll
    for (int k = 0; k < D_CONV; k++) {
        int ll = l + k - (D_CONV - 1);
        if (ll >= 0) {
            float2 uv = *(const float2*)(up + (size_t)ll * (2 * D_INNER));
            const float wk0 = (k == 0) ? w0.x : (k == 1) ? w0.y : (k == 2) ? w0.z : w0.w;
            const float wk1 = (k == 0) ? w1.x : (k == 1) ? w1.y : (k == 2) ? w1.z : w1.w;
            a0 = fmaf(uv.x, wk0, a0);
            a1 = fmaf(uv.y, wk1, a1);
        }
    }
    const float v0 = a0 * (1.0f / (1.0f + __expf(-a0)));
    const float v1 = a1 * (1.0f / (1.0f + __expf(-a1)));
    *(float2*)(out + idx) = make_float2(v0, v1);
    __nv_bfloat16 h0 = __float2bfloat16(v0), h1 = __float2bfloat16(v1);
    *(__nv_bfloat162*)(uh + idx) = __halves2bfloat162(h0, h1);
    *(__nv_bfloat162*)(ul + idx) = __halves2bfloat162(
        __float2bfloat16(v0 - __bfloat162float(h0)),
        __float2bfloat16(v1 - __bfloat162float(h1)));
}

// ---------------------------------------------------------------------------
// Chunked selective scan (R15 configuration — verified best).
// ---------------------------------------------------------------------------
__global__ __launch_bounds__(256) void scanA_kernel(
    const float* __restrict__ xdbl, const float* __restrict__ dt,
    const float* __restrict__ u, const float* __restrict__ A_log,
    float* __restrict__ hb, float* __restrict__ pp)
{
    const int lane = threadIdx.x & 31;
    const int w    = threadIdx.x >> 5;
    const int chw  = lane >> 3;
    const int sp   = lane & 7;
    const int c    = blockIdx.x * 32 + w * 4 + chw;
    const int chunk = blockIdx.y;
    const int l0   = chunk * SEG;
    const int b    = c >> 11;
    const int d    = c & (D_INNER - 1);

    const float LOG2E = 1.4426950408889634f;
    const float Ae0 = -__expf(A_log[d * D_STATE + 2 * sp])     * LOG2E;
    const float Ae1 = -__expf(A_log[d * D_STATE + 2 * sp + 1]) * LOG2E;

    const float* dtp = dt   + (size_t)b * SEQ_L * D_INNER + d;
    const float* up  = u    + (size_t)b * SEQ_L * D_INNER + d;
    const float* xb  = xdbl + (size_t)b * SEQ_L * XD + DT_RANK + 2 * sp;

    float h0 = 0.f, h1 = 0.f, P0 = 1.f, P1 = 1.f;

    float  rdt[8], ru[8];
    float2 rB[8];
#define SA_LOAD(o, slot) do {                                               \
        if ((o) < SEQ_L) {                                                  \
            rdt[slot] = dtp[(size_t)(o) * D_INNER];                         \
            ru [slot] = up [(size_t)(o) * D_INNER];                         \
            rB [slot] = *(const float2*)(xb + (size_t)(o) * XD);            \
        } else { rdt[slot] = 0.f; ru[slot] = 0.f;                           \
                 rB[slot] = make_float2(0.f, 0.f); }                        \
    } while (0)

    #pragma unroll
    for (int j = 0; j < 8; ++j) SA_LOAD(l0 + j, j);

    for (int li = 0; li < SEG; li += 8) {
        #pragma unroll
        for (int j = 0; j < 8; ++j) {
            const float  dtv = rdt[j];
            const float  uv  = ru[j];
            const float2 Bv  = rB[j];
            SA_LOAD(l0 + li + j + 8, j);

            const float cu  = dtv * uv;
            const float dA0 = exp2f(dtv * Ae0);
            const float dA1 = exp2f(dtv * Ae1);
            h0 = fmaf(dA0, h0, cu * Bv.x);
            h1 = fmaf(dA1, h1, cu * Bv.y);
            P0 *= dA0;
            P1 *= dA1;
        }
    }
#undef SA_LOAD
    const size_t o = (size_t)chunk * NCH16 + (size_t)c * D_STATE + 2 * sp;
    hb[o]     = h0;  hb[o + 1] = h1;
    pp[o]     = P0;  pp[o + 1] = P1;
}

__global__ void scanC_kernel(const float* __restrict__ hb,
                             const float* __restrict__ pp,
                             float* __restrict__ hin)
{
    int i = blockIdx.x * blockDim.x + threadIdx.x;
    if (i >= NCH16) return;
    float h = 0.f;
    hin[i] = 0.f;
    #pragma unroll
    for (int k = 1; k < NSEG; ++k) {
        h = fmaf(pp[(size_t)(k - 1) * NCH16 + i], h,
                 hb[(size_t)(k - 1) * NCH16 + i]);
        hin[(size_t)k * NCH16 + i] = h;
    }
}

__global__ __launch_bounds__(256) void scanB_kernel(
    const float* __restrict__ xdbl, const float* __restrict__ dt,
    const float* __restrict__ u, const float* __restrict__ A_log,
    const float* __restrict__ hin, float* __restrict__ y)
{
    const int lane = threadIdx.x & 31;
    const int w    = threadIdx.x >> 5;
    const int chw  = lane >> 3;
    const int sp   = lane & 7;
    const int c    = blockIdx.x * 32 + w * 4 + chw;
    const int chunk = blockIdx.y;
    const int l0   = chunk * SEG;
    const int b    = c >> 11;
    const int d    = c & (D_INNER - 1);

    const float LOG2E = 1.4426950408889634f;
    const float Ae0 = -__expf(A_log[d * D_STATE + 2 * sp])     * LOG2E;
    const float Ae1 = -__expf(A_log[d * D_STATE + 2 * sp + 1]) * LOG2E;

    const float* dtp = dt   + (size_t)b * SEQ_L * D_INNER + d;
    const float* up  = u    + (size_t)b * SEQ_L * D_INNER + d;
    const float* xb  = xdbl + (size_t)b * SEQ_L * XD + DT_RANK + 2 * sp;
    float*       yp  = y    + (size_t)b * SEQ_L * D_INNER + d;

    const size_t ho = (size_t)chunk * NCH16 + (size_t)c * D_STATE + 2 * sp;
    float h0 = hin[ho];
    float h1 = hin[ho + 1];

    float  rdt[8], ru[8];
    float2 rB[8], rC[8];
#define SB_LOAD(o, slot) do {                                               \
        if ((o) < SEQ_L) {                                                  \
            rdt[slot] = dtp[(size_t)(o) * D_INNER];                         \
            ru [slot] = up [(size_t)(o) * D_INNER];                         \
            rB [slot] = *(const float2*)(xb + (size_t)(o) * XD);            \
            rC [slot] = *(const float2*)(xb + (size_t)(o) * XD + D_STATE);  \
        } else {                                                            \
            rdt[slot] = 0.f; ru[slot] = 0.f;                                \
            rB[slot] = make_float2(0.f, 0.f);                               \
            rC[slot] = make_float2(0.f, 0.f);                               \
        }                                                                   \
    } while (0)

    #pragma unroll
    for (int j = 0; j < 8; ++j) SB_LOAD(l0 + j, j);

    for (int li = 0; li < SEG; li += 8) {
        #pragma unroll
        for (int j = 0; j < 8; ++j) {
            const int l = l0 + li + j;
            const float  dtv = rdt[j];
            const float  uv  = ru[j];
            const float2 Bv  = rB[j];
            const float2 Cv  = rC[j];
            SB_LOAD(l + 8, j);

            const float cu  = dtv * uv;
            const float dA0 = exp2f(dtv * Ae0);
            const float dA1 = exp2f(dtv * Ae1);
            h0 = fmaf(dA0, h0, cu * Bv.x);
            h1 = fmaf(dA1, h1, cu * Bv.y);

            float p = h0 * Cv.x;
            p = fmaf(h1, Cv.y, p);
            p += __shfl_xor_sync(0xffffffffu, p, 1);
            p += __shfl_xor_sync(0xffffffffu, p, 2);
            p += __shfl_xor_sync(0xffffffffu, p, 4);
            if (sp == 0) yp[(size_t)l * D_INNER] = p;
        }
    }
#undef SB_LOAD
}

// ---------------------------------------------------------------------------
// combine (4 elems/thread, vectorized): v = (y + u*D) * silu(res) -> bf16 hi/lo
// ---------------------------------------------------------------------------
__global__ void combine_kernel(const float* __restrict__ c1,
                               const float* __restrict__ uconv,
                               const float* __restrict__ Dp,
                               const float* __restrict__ y,
                               __nv_bfloat16* __restrict__ yh,
                               __nv_bfloat16* __restrict__ yl)
{
    int i4 = blockIdx.x * blockDim.x + threadIdx.x;
    if (i4 >= (M_TOT * D_INNER) / 4) return;
    const int idx = i4 * 4;
    const int d = idx & (D_INNER - 1);
    const int m = idx >> 11;
    const float4 yv = *(const float4*)(y + idx);
    const float4 uv = *(const float4*)(uconv + idx);
    const float4 dv = *(const float4*)(Dp + d);
    const float4 rv = *(const float4*)(c1 + (size_t)m * (2 * D_INNER) + D_INNER + d);

    float v[4];
    v[0] = fmaf(uv.x, dv.x, yv.x) * (rv.x * (1.0f / (1.0f + __expf(-rv.x))));
    v[1] = fmaf(uv.y, dv.y, yv.y) * (rv.y * (1.0f / (1.0f + __expf(-rv.y))));
    v[2] = fmaf(uv.z, dv.z, yv.z) * (rv.z * (1.0f / (1.0f + __expf(-rv.z))));
    v[3] = fmaf(uv.w, dv.w, yv.w) * (rv.w * (1.0f / (1.0f + __expf(-rv.w))));

    __nv_bfloat16 hb[4];
    #pragma unroll
    for (int e = 0; e < 4; ++e) hb[e] = __float2bfloat16(v[e]);
    __nv_bfloat162 hs[2] = { __halves2bfloat162(hb[0], hb[1]),
                             __halves2bfloat162(hb[2], hb[3]) };
    __nv_bfloat162 ls[2] = {
        __halves2bfloat162(__float2bfloat16(v[0] - __bfloat162float(hb[0])),
                           __float2bfloat16(v[1] - __bfloat162float(hb[1]))),
        __halves2bfloat162(__float2bfloat16(v[2] - __bfloat162float(hb[2])),
                           __float2bfloat16(v[3] - __bfloat162float(hb[3]))) };
    *(uint2*)(yh + idx) = *(uint2*)hs;
    *(uint2*)(yl + idx) = *(uint2*)ls;
}

// ---------------------------------------------------------------------------
// Launch
// ---------------------------------------------------------------------------
extern "C" void kernel_launch(void* const* d_in, const int* in_sizes, int n_in,
                              void* d_out, int out_size)
{
    const float* x       = (const float*)d_in[0];
    const float* W_in    = (const float*)d_in[1];
    const float* conv_w  = (const float*)d_in[2];
    const float* conv_b  = (const float*)d_in[3];
    const float* W_xproj = (const float*)d_in[4];
    const float* W_dt    = (const float*)d_in[5];
    const float* b_dt    = (const float*)d_in[6];
    const float* A_log   = (const float*)d_in[7];
    const float* Dp      = (const float*)d_in[8];
    const float* W_out   = (const float*)d_in[9];
    float* out = (float*)d_out;

    float *c1, *uconv, *xdbl, *dtb, *yb, *part, *hbp, *ppp, *hinp;
    __nv_bfloat16 *xh, *xl, *wth, *wtl, *woh, *wol, *yh, *yl, *uh, *ul;
    __nv_bfloat16 *wxh, *wxl, *dtlh, *dtll, *wdth, *wdtl;
    cudaGetSymbolAddress((void**)&c1,    g_c1);
    cudaGetSymbolAddress((void**)&uconv, g_uconv);
    cudaGetSymbolAddress((void**)&xdbl,  g_xdbl);
    cudaGetSymbolAddress((void**)&dtb,   g_dt);
    cudaGetSymbolAddress((void**)&yb,    g_y);
    cudaGetSymbolAddress((void**)&part,  g_part);
    cudaGetSymbolAddress((void**)&hbp,   g_hb);
    cudaGetSymbolAddress((void**)&ppp,   g_pp);
    cudaGetSymbolAddress((void**)&hinp,  g_hin);
    cudaGetSymbolAddress((void**)&xh,    g_xh);
    cudaGetSymbolAddress((void**)&xl,    g_xl);
    cudaGetSymbolAddress((void**)&wth,   g_winth);
    cudaGetSymbolAddress((void**)&wtl,   g_wintl);
    cudaGetSymbolAddress((void**)&woh,   g_woutth);
    cudaGetSymbolAddress((void**)&wol,   g_wouttl);
    cudaGetSymbolAddress((void**)&yh,    g_yh);
    cudaGetSymbolAddress((void**)&yl,    g_yl);
    cudaGetSymbolAddress((void**)&uh,    g_uh);
    cudaGetSymbolAddress((void**)&ul,    g_ul);
    cudaGetSymbolAddress((void**)&wxh,   g_wxth);
    cudaGetSymbolAddress((void**)&wxl,   g_wxtl);
    cudaGetSymbolAddress((void**)&dtlh,  g_dtlh);
    cudaGetSymbolAddress((void**)&dtll,  g_dtll);
    cudaGetSymbolAddress((void**)&wdth,  g_wdth);
    cudaGetSymbolAddress((void**)&wdtl,  g_wdtl);

    cudaFuncSetAttribute(mm_gemm_kernel,
                         cudaFuncAttributeMaxDynamicSharedMemorySize, TSMEM);

    dim3 blk(256);
    dim3 tb(32, 8);

    // launches #1-#3: conversions needed by GEMM1
    {
        int n4 = (M_TOT * D_MODEL) / 4;
        cvt_hilo_kernel<<<(n4 + 255) / 256, blk>>>((const float4*)x,
                                                   (__nv_bfloat162*)xh,
                                                   (__nv_bfloat162*)xl, n4);
        cvt_t_kernel<<<dim3((2 * D_INNER) / 32, D_MODEL / 32), tb>>>(
            W_in, wth, wtl, D_MODEL, 2 * D_INNER);
        cvt_t_kernel<<<dim3(D_MODEL / 32, D_INNER / 32), tb>>>(
            W_out, woh, wol, D_INNER, D_MODEL);
    }

    // launch #4 (ncu-profiled slot): xr = x @ W_in  (HMMA) [4096x4096x1024]
    {
        dim3 grid((2 * D_INNER) / 128, M_TOT / 128, 1);
        mm_gemm_kernel<<<grid, blk, TSMEM>>>(xh, xl, wth, wtl, c1,
                                             M_TOT, 2 * D_INNER, D_MODEL,
                                             2 * D_INNER, 2 * D_INNER, D_MODEL,
                                             nullptr, 0);
    }

    // remaining weight conversions
    {
        cvt_t_kernel<<<dim3(XD / 32, D_INNER / 32), tb>>>(
            W_xproj, wxh, wxl, D_INNER, XD);
        cvt_t_kernel<<<dim3(D_INNER / 32, DT_RANK / 32), tb>>>(
            W_dt, wdth, wdtl, DT_RANK, D_INNER);
    }

    // causal conv + silu (+ hi/lo split), 2 elems/thread
    {
        int total2 = (M_TOT * D_INNER) / 2;
        conv_silu_kernel<<<(total2 + 255) / 256, blk>>>(c1, conv_w, conv_b,
                                                        uconv, uh, ul);
    }

    // x_dbl = uconv @ W_xproj  (HMMA split-K)  [4096 x 96 x 2048]
    {
        dim3 grid(1, M_TOT / 128, KSPLIT);
        mm_gemm_kernel<<<grid, blk, TSMEM>>>(uh, ul, wxh, wxl, part,
                                             M_TOT, 128, D_INNER,
                                             XD, XD, D_INNER / KSPLIT,
                                             nullptr, 0);
        int n = M_TOT * XD;
        reduce_k_kernel<<<(n + 255) / 256, blk>>>(part, xdbl, dtlh, dtll, n);
    }

    // dt = softplus(dt_low @ W_dt + b_dt)  (HMMA)  [4096 x 2048 x 64]
    {
        dim3 grid(D_INNER / 128, M_TOT / 128, 1);
        mm_gemm_kernel<<<grid, blk, TSMEM>>>(dtlh, dtll, wdth, wdtl, dtb,
                                             M_TOT, D_INNER, DT_RANK,
                                             D_INNER, D_INNER, DT_RANK,
                                             b_dt, 1);
    }

    // chunked selective scan: A -> C -> B
    {
        scanA_kernel<<<dim3(NCH / 32, NSEG - 1), blk>>>(xdbl, dtb, uconv,
                                                        A_log, hbp, ppp);
        scanC_kernel<<<(NCH16 + 255) / 256, blk>>>(hbp, ppp, hinp);
        scanB_kernel<<<dim3(NCH / 32, NSEG), blk>>>(xdbl, dtb, uconv,
                                                    A_log, hinp, yb);
    }

    // combine -> y hi/lo (vectorized 4-wide)
    {
        int total4 = (M_TOT * D_INNER) / 4;
        combine_kernel<<<(total4 + 255) / 256, blk>>>(c1, uconv, Dp, yb, yh, yl);
    }

    // out = y @ W_out  (HMMA)  [4096 x 1024 x 2048]
    {
        dim3 grid(D_MODEL / 128, M_TOT / 128, 1);
        mm_gemm_kernel<<<grid, blk, TSMEM>>>(yh, yl, woh, wol, out,
                                             M_TOT, D_MODEL, D_INNER,
                                             D_MODEL, D_MODEL, D_INNER,
                                             nullptr, 0);
    }
}